// round 5
// baseline (speedup 1.0000x reference)
#include <cuda_runtime.h>
#include <cuda_bf16.h>
#include <math.h>

typedef unsigned long long ull;

// Problem constants
#define LSEQ 32768
#define EDIM 1024
#define NH   8
#define HD   128
#define NBLK 304                       // 2 CTAs per SM * 152 SMs
#define ROWS_PER ((LSEQ + NBLK - 1) / NBLK)   // 108
#define STAGES 4

// Scratch (no cudaMalloc allowed)
__device__ float g_q[EDIM];
__device__ float g_r[NH * EDIM];
__device__ float g_qb[NH];
__device__ float g_ypart[(size_t)NBLK * NH * EDIM];
__device__ float g_mpart[NBLK * NH];
__device__ float g_spart[NBLK * NH];
__device__ float g_yn[NH * EDIM];
__device__ float g_a[EDIM];

// ---------------- f32x2 helpers (FFMA2 path: ptxas never auto-fuses) -------
__device__ __forceinline__ ull pk2(float a, float b) {
    ull r; asm("mov.b64 %0,{%1,%2};" : "=l"(r) : "f"(a), "f"(b)); return r;
}
__device__ __forceinline__ void upk2(ull v, float& a, float& b) {
    asm("mov.b64 {%0,%1},%2;" : "=f"(a), "=f"(b) : "l"(v));
}
__device__ __forceinline__ void ffma2(ull& d, ull a, ull b) {
    asm("fma.rn.f32x2 %0,%1,%2,%0;" : "+l"(d) : "l"(a), "l"(b));
}
__device__ __forceinline__ void fmul2(ull& d, ull a) {
    asm("mul.rn.f32x2 %0,%0,%1;" : "+l"(d) : "l"(a));
}
__device__ __forceinline__ void cp_async16(void* smem, const void* gmem) {
    unsigned sa = (unsigned)__cvta_generic_to_shared(smem);
    asm volatile("cp.async.cg.shared.global [%0], [%1], 16;" :: "r"(sa), "l"(gmem));
}

// ---------------------------------------------------------------------------
// Generic mat-vec: out[row] = dot(W[w_row_off+row, :], vec(row)) + bias[b_off+row]
// ---------------------------------------------------------------------------
__global__ void __launch_bounds__(256) matvec_kernel(
    const float* __restrict__ W, const float* __restrict__ vec,
    const float* __restrict__ bias, float* __restrict__ out,
    int w_row_off, int b_off, int head_mode)
{
    int warp = threadIdx.x >> 5;
    int lane = threadIdx.x & 31;
    int row  = blockIdx.x * 8 + warp;
    if (row >= EDIM) return;

    const float* v  = vec + (head_mode ? (size_t)(row >> 7) * EDIM : 0);
    const float4* wr = (const float4*)(W + (size_t)(w_row_off + row) * EDIM);
    const float4* v4 = (const float4*)v;

    float acc = 0.f;
    #pragma unroll
    for (int j = 0; j < 8; j++) {
        float4 a = wr[lane + 32 * j];
        float4 b = v4[lane + 32 * j];
        acc = fmaf(a.x, b.x, acc);
        acc = fmaf(a.y, b.y, acc);
        acc = fmaf(a.z, b.z, acc);
        acc = fmaf(a.w, b.w, acc);
    }
    #pragma unroll
    for (int o = 16; o; o >>= 1) acc += __shfl_xor_sync(0xffffffffu, acc, o);
    if (lane == 0) out[row] = acc + bias[b_off + row];
}

// ---------------------------------------------------------------------------
// r[h,e] = (1/sqrt(HD)) * sum_d q[h*HD+d] * W[EDIM + h*HD + d, e]; qb likewise
// ---------------------------------------------------------------------------
__global__ void __launch_bounds__(256) compute_r_kernel(
    const float* __restrict__ W, const float* __restrict__ b)
{
    const float scale = 0.08838834764831845f; // 1/sqrt(128)
    int idx = blockIdx.x * 256 + threadIdx.x; // 0..8191
    int h = idx >> 10;
    int e = idx & 1023;

    float acc = 0.f;
    const float* qh = g_q + h * HD;
    const float* wp = W + (size_t)(EDIM + h * HD) * EDIM + e;
    #pragma unroll 8
    for (int d = 0; d < HD; d++) {
        acc = fmaf(qh[d], wp[(size_t)d * EDIM], acc);
    }
    g_r[idx] = acc * scale;

    if (idx < NH) {
        float qq = 0.f;
        const float* qhh = g_q + idx * HD;
        const float* bp  = b + EDIM + idx * HD;
        for (int d = 0; d < HD; d++) qq = fmaf(qhh[d], bp[d], qq);
        g_qb[idx] = qq * scale;
    }
}

// ---------------------------------------------------------------------------
// Main flash pass, 2 heads per thread + FFMA2 + cp.async pipeline.
// Warp w: head-pair g=w>>1 (heads 2g,2g+1), half=w&1 (row columns half*512..+512).
// Thread slice: 16 floats { half*512 + 128j + 4*lane + c }, j=0..3.
// Logits combined across the 2 warps of a pair via a tiny shared scoreboard.
// ---------------------------------------------------------------------------
__global__ void __launch_bounds__(256, 2) attn_main_kernel(const float* __restrict__ x)
{
    __shared__ __align__(16) float xs[STAGES][EDIM];
    __shared__ float ps[2][4][2][2];   // [parity][pair][half][head-of-pair]

    int tid  = threadIdx.x;
    int w    = tid >> 5;
    int lane = tid & 31;
    int g    = w >> 1;
    int half = w & 1;
    int h0   = 2 * g, h1 = 2 * g + 1;
    int blk  = blockIdx.x;
    int row0 = blk * ROWS_PER;
    int nrows = min(LSEQ - row0, ROWS_PER);

    int base = half * 512 + 4 * lane;

    // r slices for both heads, packed as f32 pairs
    ull r0p[8], r1p[8];
    #pragma unroll
    for (int j = 0; j < 4; j++) {
        ulonglong2 a = *(const ulonglong2*)(g_r + h0 * EDIM + base + 128 * j);
        r0p[2 * j] = a.x; r0p[2 * j + 1] = a.y;
        ulonglong2 b = *(const ulonglong2*)(g_r + h1 * EDIM + base + 128 * j);
        r1p[2 * j] = b.x; r1p[2 * j + 1] = b.y;
    }
    const float qb0 = g_qb[h0];
    const float qb1 = g_qb[h1];

    ull y0p[8], y1p[8];
    #pragma unroll
    for (int j = 0; j < 8; j++) { y0p[j] = 0ull; y1p[j] = 0ull; }
    float m0 = -3.4e38f, S0 = 0.f, m1 = -3.4e38f, S1 = 0.f;

    const float4* xg = (const float4*)x;   // row i at xg[i*256 + tid]

    // prologue: stage first STAGES-1 rows
    #pragma unroll
    for (int d = 0; d < STAGES - 1; d++) {
        if (d < nrows)
            cp_async16(&xs[d][tid * 4], &xg[(size_t)(row0 + d) * 256 + tid]);
        asm volatile("cp.async.commit_group;");
    }

    for (int i = 0; i < nrows; i++) {
        int st = i & (STAGES - 1);
        asm volatile("cp.async.wait_group %0;" :: "n"(STAGES - 2));
        __syncthreads();   // row i staged + ps[p] from row i-2 fully consumed

        // load thread slice, keep in regs
        ull xv[8];
        #pragma unroll
        for (int j = 0; j < 4; j++) {
            ulonglong2 v = *(const ulonglong2*)&xs[st][base + 128 * j];
            xv[2 * j] = v.x; xv[2 * j + 1] = v.y;
        }

        // dot partials for both heads (16 FFMA2)
        ull a0 = 0ull, a1 = 0ull;
        #pragma unroll
        for (int j = 0; j < 8; j++) { ffma2(a0, r0p[j], xv[j]); ffma2(a1, r1p[j], xv[j]); }
        float p0a, p0b, p1a, p1b;
        upk2(a0, p0a, p0b); upk2(a1, p1a, p1b);
        float s0 = p0a + p0b, s1 = p1a + p1b;
        #pragma unroll
        for (int o = 16; o; o >>= 1) {
            s0 += __shfl_xor_sync(0xffffffffu, s0, o);
            s1 += __shfl_xor_sync(0xffffffffu, s1, o);
        }
        int p = i & 1;
        if (lane == 0) { ps[p][g][half][0] = s0; ps[p][g][half][1] = s1; }

        // prefetch row i+STAGES-1
        int nr = i + STAGES - 1;
        if (nr < nrows)
            cp_async16(&xs[nr & (STAGES - 1)][tid * 4], &xg[(size_t)(row0 + nr) * 256 + tid]);
        asm volatile("cp.async.commit_group;");

        __syncthreads();   // publish ps[p]

        float fs0 = ps[p][g][0][0] + ps[p][g][1][0] + qb0;
        float fs1 = ps[p][g][0][1] + ps[p][g][1][1] + qb1;

        // online softmax + y update, head 2g
        float w0;
        if (fs0 > m0) {
            float c = __expf(m0 - fs0);
            S0 *= c;
            ull cp = pk2(c, c);
            #pragma unroll
            for (int j = 0; j < 8; j++) fmul2(y0p[j], cp);
            m0 = fs0; w0 = 1.f;
        } else {
            w0 = __expf(fs0 - m0);
        }
        S0 += w0;
        {
            ull wp = pk2(w0, w0);
            #pragma unroll
            for (int j = 0; j < 8; j++) ffma2(y0p[j], wp, xv[j]);
        }
        // head 2g+1
        float w1;
        if (fs1 > m1) {
            float c = __expf(m1 - fs1);
            S1 *= c;
            ull cp = pk2(c, c);
            #pragma unroll
            for (int j = 0; j < 8; j++) fmul2(y1p[j], cp);
            m1 = fs1; w1 = 1.f;
        } else {
            w1 = __expf(fs1 - m1);
        }
        S1 += w1;
        {
            ull wp = pk2(w1, w1);
            #pragma unroll
            for (int j = 0; j < 8; j++) ffma2(y1p[j], wp, xv[j]);
        }
    }

    // write partials
    float* ypb = g_ypart + (size_t)blk * (NH * EDIM);
    #pragma unroll
    for (int j = 0; j < 4; j++) {
        ulonglong2 v0; v0.x = y0p[2 * j]; v0.y = y0p[2 * j + 1];
        *(ulonglong2*)(ypb + h0 * EDIM + base + 128 * j) = v0;
        ulonglong2 v1; v1.x = y1p[2 * j]; v1.y = y1p[2 * j + 1];
        *(ulonglong2*)(ypb + h1 * EDIM + base + 128 * j) = v1;
    }
    if (half == 0 && lane == 0) {
        g_mpart[blk * NH + h0] = m0;  g_spart[blk * NH + h0] = S0;
        g_mpart[blk * NH + h1] = m1;  g_spart[blk * NH + h1] = S1;
    }
}

// ---------------------------------------------------------------------------
// Fused: per-head softmax-state combine + normalized partial reduction.
// 32 blocks; block b covers positions [b*256, b*256+256) of yn (head h=b>>2).
// ---------------------------------------------------------------------------
__global__ void __launch_bounds__(256) reduce_y_kernel()
{
    __shared__ float cs[NBLK];
    __shared__ float sh[2];
    int tid = threadIdx.x;
    int idx = blockIdx.x * 256 + tid;       // 0..8191
    int h   = blockIdx.x >> 2;              // uniform per block

    if (tid < 32) {
        float m = -3.4e38f;
        for (int g2 = tid; g2 < NBLK; g2 += 32)
            m = fmaxf(m, g_mpart[g2 * NH + h]);
        #pragma unroll
        for (int o = 16; o; o >>= 1) m = fmaxf(m, __shfl_xor_sync(0xffffffffu, m, o));
        float S = 0.f;
        for (int g2 = tid; g2 < NBLK; g2 += 32)
            S = fmaf(__expf(g_mpart[g2 * NH + h] - m), g_spart[g2 * NH + h], S);
        #pragma unroll
        for (int o = 16; o; o >>= 1) S += __shfl_xor_sync(0xffffffffu, S, o);
        if (tid == 0) { sh[0] = m; sh[1] = 1.f / S; }
    }
    __syncthreads();
    float M = sh[0], inv = sh[1];
    for (int g2 = tid; g2 < NBLK; g2 += 256)
        cs[g2] = __expf(g_mpart[g2 * NH + h] - M) * inv;
    __syncthreads();

    float acc = 0.f;
    #pragma unroll 4
    for (int g2 = 0; g2 < NBLK; g2++)
        acc = fmaf(cs[g2], g_ypart[(size_t)g2 * (NH * EDIM) + idx], acc);
    g_yn[idx] = acc;
}

// ---------------------------------------------------------------------------
extern "C" void kernel_launch(void* const* d_in, const int* in_sizes, int n_in,
                              void* d_out, int out_size)
{
    const float* x    = (const float*)d_in[0];  // [32768, 1024]
    const float* win  = (const float*)d_in[1];  // [3072, 1024]
    const float* bin  = (const float*)d_in[2];  // [3072]
    const float* wout = (const float*)d_in[3];  // [1024, 1024]
    const float* bout = (const float*)d_in[4];  // [1024]
    float* out = (float*)d_out;                 // [1024]

    float* q  = nullptr; cudaGetSymbolAddress((void**)&q,  g_q);
    float* yn = nullptr; cudaGetSymbolAddress((void**)&yn, g_yn);
    float* a  = nullptr; cudaGetSymbolAddress((void**)&a,  g_a);

    // 1) q = x[0] @ Wq^T + bq
    matvec_kernel<<<128, 256>>>(win, x, bin, q, 0, 0, 0);
    // 2) r[h,:] = (q_h @ Wk_h) / sqrt(D); qb[h] = (q_h . bk_h) / sqrt(D)
    compute_r_kernel<<<32, 256>>>(win, bin);
    // 3) main streaming pass: logits + online softmax + weighted x sums
    attn_main_kernel<<<NBLK, 256>>>(x);
    // 4) combine softmax states + reduce partials -> yn (coef fold eliminates a launch)
    reduce_y_kernel<<<32, 256>>>();
    // 5) a[i] = Wv[i,:] . yn[i>>7] + bv[i]
    matvec_kernel<<<128, 256>>>(win, yn, bin, a, 2 * EDIM, 2 * EDIM, 1);
    // 6) out = Wo @ a + bo
    matvec_kernel<<<128, 256>>>(wout, a, bout, out, 0, 0, 0);
}

// round 6
// speedup vs baseline: 1.0214x; 1.0214x over previous
#include <cuda_runtime.h>
#include <cuda_bf16.h>
#include <math.h>

typedef unsigned long long ull;

// Problem constants
#define LSEQ 32768
#define EDIM 1024
#define NH   8
#define HD   128
#define NBLK 304                       // 2 CTAs per SM * 152 SMs
#define ROWS_PER ((LSEQ + NBLK - 1) / NBLK)   // 108
#define STAGES 4

// Scratch (no cudaMalloc allowed)
__device__ float g_q[EDIM];
__device__ float g_r[NH * EDIM];
__device__ float g_qb[NH];
__device__ float g_ypart[(size_t)NBLK * NH * EDIM];
__device__ float g_mpart[NBLK * NH];
__device__ float g_spart[NBLK * NH];
__device__ float g_yn[NH * EDIM];
__device__ float g_a[EDIM];

// ---------------- f32x2 helpers (FFMA2 path: ptxas never auto-fuses) -------
__device__ __forceinline__ ull pk2(float a, float b) {
    ull r; asm("mov.b64 %0,{%1,%2};" : "=l"(r) : "f"(a), "f"(b)); return r;
}
__device__ __forceinline__ void upk2(ull v, float& a, float& b) {
    asm("mov.b64 {%0,%1},%2;" : "=f"(a), "=f"(b) : "l"(v));
}
__device__ __forceinline__ void ffma2(ull& d, ull a, ull b) {
    asm("fma.rn.f32x2 %0,%1,%2,%0;" : "+l"(d) : "l"(a), "l"(b));
}
__device__ __forceinline__ void fmul2(ull& d, ull a) {
    asm("mul.rn.f32x2 %0,%0,%1;" : "+l"(d) : "l"(a));
}
__device__ __forceinline__ void cp_async16(void* smem, const void* gmem) {
    unsigned sa = (unsigned)__cvta_generic_to_shared(smem);
    asm volatile("cp.async.cg.shared.global [%0], [%1], 16;" :: "r"(sa), "l"(gmem));
}

// ---------------------------------------------------------------------------
// Generic mat-vec: out[row] = dot(W[w_row_off+row, :], vec(row)) + bias[b_off+row]
// ---------------------------------------------------------------------------
__global__ void __launch_bounds__(256) matvec_kernel(
    const float* __restrict__ W, const float* __restrict__ vec,
    const float* __restrict__ bias, float* __restrict__ out,
    int w_row_off, int b_off, int head_mode)
{
    int warp = threadIdx.x >> 5;
    int lane = threadIdx.x & 31;
    int row  = blockIdx.x * 8 + warp;
    if (row >= EDIM) return;

    const float* v  = vec + (head_mode ? (size_t)(row >> 7) * EDIM : 0);
    const float4* wr = (const float4*)(W + (size_t)(w_row_off + row) * EDIM);
    const float4* v4 = (const float4*)v;

    float acc = 0.f;
    #pragma unroll
    for (int j = 0; j < 8; j++) {
        float4 a = wr[lane + 32 * j];
        float4 b = v4[lane + 32 * j];
        acc = fmaf(a.x, b.x, acc);
        acc = fmaf(a.y, b.y, acc);
        acc = fmaf(a.z, b.z, acc);
        acc = fmaf(a.w, b.w, acc);
    }
    #pragma unroll
    for (int o = 16; o; o >>= 1) acc += __shfl_xor_sync(0xffffffffu, acc, o);
    if (lane == 0) out[row] = acc + bias[b_off + row];
}

// ---------------------------------------------------------------------------
// r[h,e] = (1/sqrt(HD)) * sum_d q[h*HD+d] * W[EDIM + h*HD + d, e]; qb likewise
// ---------------------------------------------------------------------------
__global__ void __launch_bounds__(256) compute_r_kernel(
    const float* __restrict__ W, const float* __restrict__ b)
{
    const float scale = 0.08838834764831845f; // 1/sqrt(128)
    int idx = blockIdx.x * 256 + threadIdx.x; // 0..8191
    int h = idx >> 10;
    int e = idx & 1023;

    float acc = 0.f;
    const float* qh = g_q + h * HD;
    const float* wp = W + (size_t)(EDIM + h * HD) * EDIM + e;
    #pragma unroll 8
    for (int d = 0; d < HD; d++) {
        acc = fmaf(qh[d], wp[(size_t)d * EDIM], acc);
    }
    g_r[idx] = acc * scale;

    if (idx < NH) {
        float qq = 0.f;
        const float* qhh = g_q + idx * HD;
        const float* bp  = b + EDIM + idx * HD;
        for (int d = 0; d < HD; d++) qq = fmaf(qhh[d], bp[d], qq);
        g_qb[idx] = qq * scale;
    }
}

// ---------------------------------------------------------------------------
// Main flash pass, 2 heads per thread + FFMA2 + cp.async pipeline.
// Warp w: head-pair g=w>>1 (heads 2g,2g+1), half=w&1 (row columns half*512..+512).
// Thread slice: 16 floats { half*512 + 128j + 4*lane + c }, j=0..3.
// Logits combined across the 2 warps of a pair via a tiny shared scoreboard.
// ---------------------------------------------------------------------------
__global__ void __launch_bounds__(256, 2) attn_main_kernel(const float* __restrict__ x)
{
    __shared__ __align__(16) float xs[STAGES][EDIM];
    __shared__ float ps[2][4][2][2];   // [parity][pair][half][head-of-pair]

    int tid  = threadIdx.x;
    int w    = tid >> 5;
    int lane = tid & 31;
    int g    = w >> 1;
    int half = w & 1;
    int h0   = 2 * g, h1 = 2 * g + 1;
    int blk  = blockIdx.x;
    int row0 = blk * ROWS_PER;
    int nrows = min(LSEQ - row0, ROWS_PER);

    int base = half * 512 + 4 * lane;

    // r slices for both heads, packed as f32 pairs
    ull r0p[8], r1p[8];
    #pragma unroll
    for (int j = 0; j < 4; j++) {
        ulonglong2 a = *(const ulonglong2*)(g_r + h0 * EDIM + base + 128 * j);
        r0p[2 * j] = a.x; r0p[2 * j + 1] = a.y;
        ulonglong2 b = *(const ulonglong2*)(g_r + h1 * EDIM + base + 128 * j);
        r1p[2 * j] = b.x; r1p[2 * j + 1] = b.y;
    }
    const float qb0 = g_qb[h0];
    const float qb1 = g_qb[h1];

    ull y0p[8], y1p[8];
    #pragma unroll
    for (int j = 0; j < 8; j++) { y0p[j] = 0ull; y1p[j] = 0ull; }
    float m0 = -3.4e38f, S0 = 0.f, m1 = -3.4e38f, S1 = 0.f;

    const float4* xg = (const float4*)x;   // row i at xg[i*256 + tid]

    // prologue: stage first STAGES-1 rows
    #pragma unroll
    for (int d = 0; d < STAGES - 1; d++) {
        if (d < nrows)
            cp_async16(&xs[d][tid * 4], &xg[(size_t)(row0 + d) * 256 + tid]);
        asm volatile("cp.async.commit_group;");
    }

    for (int i = 0; i < nrows; i++) {
        int st = i & (STAGES - 1);
        asm volatile("cp.async.wait_group %0;" :: "n"(STAGES - 2));
        __syncthreads();   // row i staged + ps[p] from row i-2 fully consumed

        // load thread slice, keep in regs
        ull xv[8];
        #pragma unroll
        for (int j = 0; j < 4; j++) {
            ulonglong2 v = *(const ulonglong2*)&xs[st][base + 128 * j];
            xv[2 * j] = v.x; xv[2 * j + 1] = v.y;
        }

        // dot partials for both heads (16 FFMA2)
        ull a0 = 0ull, a1 = 0ull;
        #pragma unroll
        for (int j = 0; j < 8; j++) { ffma2(a0, r0p[j], xv[j]); ffma2(a1, r1p[j], xv[j]); }
        float p0a, p0b, p1a, p1b;
        upk2(a0, p0a, p0b); upk2(a1, p1a, p1b);
        float s0 = p0a + p0b, s1 = p1a + p1b;
        #pragma unroll
        for (int o = 16; o; o >>= 1) {
            s0 += __shfl_xor_sync(0xffffffffu, s0, o);
            s1 += __shfl_xor_sync(0xffffffffu, s1, o);
        }
        int p = i & 1;
        if (lane == 0) { ps[p][g][half][0] = s0; ps[p][g][half][1] = s1; }

        // prefetch row i+STAGES-1
        int nr = i + STAGES - 1;
        if (nr < nrows)
            cp_async16(&xs[nr & (STAGES - 1)][tid * 4], &xg[(size_t)(row0 + nr) * 256 + tid]);
        asm volatile("cp.async.commit_group;");

        __syncthreads();   // publish ps[p]

        float fs0 = ps[p][g][0][0] + ps[p][g][1][0] + qb0;
        float fs1 = ps[p][g][0][1] + ps[p][g][1][1] + qb1;

        // online softmax + y update, head 2g
        float w0;
        if (fs0 > m0) {
            float c = __expf(m0 - fs0);
            S0 *= c;
            ull cp = pk2(c, c);
            #pragma unroll
            for (int j = 0; j < 8; j++) fmul2(y0p[j], cp);
            m0 = fs0; w0 = 1.f;
        } else {
            w0 = __expf(fs0 - m0);
        }
        S0 += w0;
        {
            ull wp = pk2(w0, w0);
            #pragma unroll
            for (int j = 0; j < 8; j++) ffma2(y0p[j], wp, xv[j]);
        }
        // head 2g+1
        float w1;
        if (fs1 > m1) {
            float c = __expf(m1 - fs1);
            S1 *= c;
            ull cp = pk2(c, c);
            #pragma unroll
            for (int j = 0; j < 8; j++) fmul2(y1p[j], cp);
            m1 = fs1; w1 = 1.f;
        } else {
            w1 = __expf(fs1 - m1);
        }
        S1 += w1;
        {
            ull wp = pk2(w1, w1);
            #pragma unroll
            for (int j = 0; j < 8; j++) ffma2(y1p[j], wp, xv[j]);
        }
    }

    // write partials
    float* ypb = g_ypart + (size_t)blk * (NH * EDIM);
    #pragma unroll
    for (int j = 0; j < 4; j++) {
        ulonglong2 v0; v0.x = y0p[2 * j]; v0.y = y0p[2 * j + 1];
        *(ulonglong2*)(ypb + h0 * EDIM + base + 128 * j) = v0;
        ulonglong2 v1; v1.x = y1p[2 * j]; v1.y = y1p[2 * j + 1];
        *(ulonglong2*)(ypb + h1 * EDIM + base + 128 * j) = v1;
    }
    if (half == 0 && lane == 0) {
        g_mpart[blk * NH + h0] = m0;  g_spart[blk * NH + h0] = S0;
        g_mpart[blk * NH + h1] = m1;  g_spart[blk * NH + h1] = S1;
    }
}

// ---------------------------------------------------------------------------
// Fused: per-head softmax-state combine + normalized partial reduction.
// 32 blocks; block b covers positions [b*256, b*256+256) of yn (head h=b>>2).
// ---------------------------------------------------------------------------
__global__ void __launch_bounds__(256) reduce_y_kernel()
{
    __shared__ float cs[NBLK];
    __shared__ float sh[2];
    int tid = threadIdx.x;
    int idx = blockIdx.x * 256 + tid;       // 0..8191
    int h   = blockIdx.x >> 2;              // uniform per block

    if (tid < 32) {
        float m = -3.4e38f;
        for (int g2 = tid; g2 < NBLK; g2 += 32)
            m = fmaxf(m, g_mpart[g2 * NH + h]);
        #pragma unroll
        for (int o = 16; o; o >>= 1) m = fmaxf(m, __shfl_xor_sync(0xffffffffu, m, o));
        float S = 0.f;
        for (int g2 = tid; g2 < NBLK; g2 += 32)
            S = fmaf(__expf(g_mpart[g2 * NH + h] - m), g_spart[g2 * NH + h], S);
        #pragma unroll
        for (int o = 16; o; o >>= 1) S += __shfl_xor_sync(0xffffffffu, S, o);
        if (tid == 0) { sh[0] = m; sh[1] = 1.f / S; }
    }
    __syncthreads();
    float M = sh[0], inv = sh[1];
    for (int g2 = tid; g2 < NBLK; g2 += 256)
        cs[g2] = __expf(g_mpart[g2 * NH + h] - M) * inv;
    __syncthreads();

    float acc = 0.f;
    #pragma unroll 4
    for (int g2 = 0; g2 < NBLK; g2++)
        acc = fmaf(cs[g2], g_ypart[(size_t)g2 * (NH * EDIM) + idx], acc);
    g_yn[idx] = acc;
}

// ---------------------------------------------------------------------------
extern "C" void kernel_launch(void* const* d_in, const int* in_sizes, int n_in,
                              void* d_out, int out_size)
{
    const float* x    = (const float*)d_in[0];  // [32768, 1024]
    const float* win  = (const float*)d_in[1];  // [3072, 1024]
    const float* bin  = (const float*)d_in[2];  // [3072]
    const float* wout = (const float*)d_in[3];  // [1024, 1024]
    const float* bout = (const float*)d_in[4];  // [1024]
    float* out = (float*)d_out;                 // [1024]

    float* q  = nullptr; cudaGetSymbolAddress((void**)&q,  g_q);
    float* yn = nullptr; cudaGetSymbolAddress((void**)&yn, g_yn);
    float* a  = nullptr; cudaGetSymbolAddress((void**)&a,  g_a);

    // 1) q = x[0] @ Wq^T + bq
    matvec_kernel<<<128, 256>>>(win, x, bin, q, 0, 0, 0);
    // 2) r[h,:] = (q_h @ Wk_h) / sqrt(D); qb[h] = (q_h . bk_h) / sqrt(D)
    compute_r_kernel<<<32, 256>>>(win, bin);
    // 3) main streaming pass: logits + online softmax + weighted x sums
    attn_main_kernel<<<NBLK, 256>>>(x);
    // 4) combine softmax states + reduce partials -> yn (coef fold eliminates a launch)
    reduce_y_kernel<<<32, 256>>>();
    // 5) a[i] = Wv[i,:] . yn[i>>7] + bv[i]
    matvec_kernel<<<128, 256>>>(win, yn, bin, a, 2 * EDIM, 2 * EDIM, 1);
    // 6) out = Wo @ a + bo
    matvec_kernel<<<128, 256>>>(wout, a, bout, out, 0, 0, 0);
}